// round 3
// baseline (speedup 1.0000x reference)
#include <cuda_runtime.h>
#include <cstdint>

// FPS: B=2 batches, Npb=131072 points each, stride=32 -> M=4096 samples.
// 64 CTAs per batch * 256 threads * 8 points/thread; all point state lives in
// registers. Per-round batch-wide argmax via candidate slots in device global
// memory (L2) with a release/acquire seq protocol, parity double-buffered.
// All 128 CTAs fit in one wave on 148 SMs -> the spin barrier is safe.

#define CPB    64     // CTAs per batch
#define TPB    256    // threads per CTA
#define PPT    8      // points per thread
#define NBATCH 2
#define NPB    131072 // points per batch  (= CPB*TPB*PPT)
#define MSAMP  4096   // samples per batch (= ceil(NPB/32))
#define NW     (TPB / 32)

struct __align__(32) Cand {
    unsigned long long key;   // (dist_bits << 32) | (0x7FFFFFFF - idx)
    float x, y, z;
    unsigned seq;
    unsigned pad;
};

__device__ Cand g_cand[2][NBATCH][CPB];   // [round parity][batch][cta]

__device__ __forceinline__ unsigned ld_acq(const unsigned* p) {
    unsigned v;
    asm volatile("ld.acquire.gpu.global.u32 %0, [%1];" : "=r"(v) : "l"(p));
    return v;
}
__device__ __forceinline__ void st_rel(unsigned* p, unsigned v) {
    asm volatile("st.release.gpu.global.u32 [%0], %1;" :: "l"(p), "r"(v));
}
__device__ __forceinline__ unsigned long long ld_rlx64(const unsigned long long* p) {
    unsigned long long v;
    asm volatile("ld.relaxed.gpu.global.u64 %0, [%1];" : "=l"(v) : "l"(p));
    return v;
}
__device__ __forceinline__ float ld_rlxf(const float* p) {
    float v;
    asm volatile("ld.relaxed.gpu.global.f32 %0, [%1];" : "=f"(v) : "l"(p));
    return v;
}
__device__ __forceinline__ void st_rlx64(unsigned long long* p, unsigned long long v) {
    asm volatile("st.relaxed.gpu.global.u64 [%0], %1;" :: "l"(p), "l"(v));
}
__device__ __forceinline__ void st_rlxf(float* p, float v) {
    asm volatile("st.relaxed.gpu.global.f32 [%0], %1;" :: "l"(p), "f"(v));
}

__global__ void __launch_bounds__(TPB, 1)
fps_kernel(const float4* __restrict__ pts, float* __restrict__ out)
{
    const int b   = blockIdx.x >> 6;      // / CPB
    const int c   = blockIdx.x & (CPB - 1);
    const int tid = threadIdx.x;
    const int wid = tid >> 5;

    const int lbase = c * (TPB * PPT);    // in-batch base index of this CTA
    const int gbase = b * NPB + lbase;

    // Register-resident point state
    float x[PPT], y[PPT], z[PPT], dist[PPT];
    unsigned tail[PPT];
#pragma unroll
    for (int p = 0; p < PPT; ++p) {
        float4 v = pts[gbase + p * TPB + tid];
        x[p] = v.y; y[p] = v.z; z[p] = v.w;
        dist[p] = 3.402823466e38f;        // +FLT_MAX: round 1 min == d(.,p0)
        tail[p] = 0x7FFFFFFFu - (unsigned)(lbase + p * TPB + tid);
    }

    // Seed sample = point 0 of the batch (pointops convention)
    float4 p0 = pts[(size_t)b * NPB];
    float sx = p0.y, sy = p0.z, sz = p0.w;

    if (c == 0 && tid == 0) {
        float* o = out + (size_t)b * MSAMP * 4;
        o[0] = p0.x; o[1] = p0.y; o[2] = p0.z; o[3] = p0.w;
    }

    __shared__ unsigned long long swkey[NW];
    __shared__ float swx[NW], swy[NW], swz[NW];
    __shared__ unsigned long long skey[CPB];
    __shared__ float scx[CPB], scy[CPB], scz[CPB];
    __shared__ float s_new[3];

    for (int t = 1; t < MSAMP; ++t) {
        // ---- local dist update + per-thread argmax ----
        unsigned long long bk = 0ULL;
        float bx = 0.f, by = 0.f, bz = 0.f;
#pragma unroll
        for (int p = 0; p < PPT; ++p) {
            float dx = x[p] - sx;
            float dy = y[p] - sy;
            float dz = z[p] - sz;
            // no-FMA, left-to-right: (dx*dx + dy*dy) + dz*dz — matches the
            // reference's unfused f32 evaluation order exactly.
            float d = __fadd_rn(__fadd_rn(__fmul_rn(dx, dx), __fmul_rn(dy, dy)),
                                __fmul_rn(dz, dz));
            float nd = fminf(dist[p], d);
            dist[p] = nd;
            unsigned long long k =
                ((unsigned long long)__float_as_uint(nd) << 32) | tail[p];
            if (k > bk) { bk = k; bx = x[p]; by = y[p]; bz = z[p]; }
        }

        // ---- warp argmax (keys are unique -> exactly one winning lane) ----
        unsigned long long wk = bk;
#pragma unroll
        for (int o = 16; o > 0; o >>= 1) {
            unsigned long long other = __shfl_xor_sync(0xFFFFFFFFu, wk, o);
            if (other > wk) wk = other;
        }
        if (wk == bk) { swkey[wid] = bk; swx[wid] = bx; swy[wid] = by; swz[wid] = bz; }
        __syncthreads();

        // ---- block argmax + publish this CTA's candidate ----
        if (tid == 0) {
            unsigned long long k = swkey[0]; int s = 0;
#pragma unroll
            for (int i = 1; i < NW; ++i)
                if (swkey[i] > k) { k = swkey[i]; s = i; }
            Cand* cd = &g_cand[t & 1][b][c];
            st_rlx64(&cd->key, k);
            st_rlxf(&cd->x, swx[s]);
            st_rlxf(&cd->y, swy[s]);
            st_rlxf(&cd->z, swz[s]);
            st_rel(&cd->seq, (unsigned)t);    // release: payload visible first
        }

        // ---- consume all CPB candidates of this batch (1 slot per thread) ----
        if (tid < CPB) {
            Cand* cd = &g_cand[t & 1][b][tid];
            while (ld_acq(&cd->seq) != (unsigned)t) { /* spin */ }
            skey[tid] = ld_rlx64(&cd->key);
            scx[tid] = ld_rlxf(&cd->x);
            scy[tid] = ld_rlxf(&cd->y);
            scz[tid] = ld_rlxf(&cd->z);
        }
        __syncthreads();

        // ---- batch-wide argmax over CPB candidates ----
        if (tid < 32) {
            unsigned long long k0 = skey[tid], k1 = skey[tid + 32];
            unsigned long long kk = k0; int slot = tid;
            if (k1 > k0) { kk = k1; slot = tid + 32; }
#pragma unroll
            for (int o = 16; o > 0; o >>= 1) {
                unsigned long long ok = __shfl_xor_sync(0xFFFFFFFFu, kk, o);
                int os = __shfl_xor_sync(0xFFFFFFFFu, slot, o);
                if (ok > kk) { kk = ok; slot = os; }
            }
            if (tid == 0) {
                float wx = scx[slot], wy = scy[slot], wz = scz[slot];
                s_new[0] = wx; s_new[1] = wy; s_new[2] = wz;
                if (c == 0) {
                    float* o = out + ((size_t)b * MSAMP + t) * 4;
                    o[0] = (float)b; o[1] = wx; o[2] = wy; o[3] = wz;
                }
            }
        }
        __syncthreads();
        sx = s_new[0]; sy = s_new[1]; sz = s_new[2];
    }
}

extern "C" void kernel_launch(void* const* d_in, const int* in_sizes, int n_in,
                              void* d_out, int out_size) {
    (void)in_sizes; (void)n_in; (void)out_size;
    const float4* pts = (const float4*)d_in[0];
    // Geometry is fixed by the problem instance: N=262144, B=2, stride=32.
    fps_kernel<<<NBATCH * CPB, TPB>>>(pts, (float*)d_out);
}

// round 4
// speedup vs baseline: 1.5663x; 1.5663x over previous
#include <cuda_runtime.h>
#include <cstdint>

// FPS: B=2 batches, Npb=131072 pts each, stride=32 -> M=4096 samples.
// 32 CTAs/batch * 512 threads * 8 pts/thread, all point state in registers.
// Per-round batch argmax: each CTA publishes one 32B self-validating packet
// (two 16B halves, each embedding a (round,tail) freshness word) to L2;
// warp 0 of every CTA polls all 32 slots (one per lane) with volatile v4
// loads -- flag and payload arrive in the SAME 16B access, so there is no
// second round trip and no acquire/release needed. Parity double-buffered;
// all 64 CTAs are co-resident in one wave, so the spin is deadlock-free.

#define NBATCH 2
#define CPB    32     // CTAs per batch (== warp size: 1 slot per lane)
#define TPB    512
#define PPT    8
#define NPB    131072 // = CPB*TPB*PPT
#define MSAMP  4096
#define NW     (TPB / 32)

struct __align__(32) Slot { uint4 a; uint4 b; };
// halfA = {dist_bits, w, x, y}   halfB = {z, w, 0, 0}
// w = (t << 17) | (tail & 0x1FFFF),  tail = 0x7FFFFFFF - in_batch_idx

__device__ Slot g_slot[2][NBATCH][CPB];   // [round parity][batch][cta]

__device__ __forceinline__ uint4 ldv(const uint4* p) {
    uint4 v;
    asm volatile("ld.volatile.global.v4.u32 {%0,%1,%2,%3}, [%4];"
                 : "=r"(v.x), "=r"(v.y), "=r"(v.z), "=r"(v.w) : "l"(p));
    return v;
}
__device__ __forceinline__ void stv(uint4* p, uint4 v) {
    asm volatile("st.volatile.global.v4.u32 [%0], {%1,%2,%3,%4};"
                 :: "l"(p), "r"(v.x), "r"(v.y), "r"(v.z), "r"(v.w));
}

__global__ void __launch_bounds__(TPB, 1)
fps_kernel(const float4* __restrict__ pts, float* __restrict__ out)
{
    const int c    = blockIdx.x;          // CTA within batch (0..31)
    const int b    = blockIdx.y;          // batch
    const int tid  = threadIdx.x;
    const int lane = tid & 31;
    const int wid  = tid >> 5;

    const int lbase = c * (TPB * PPT);    // in-batch base index of this CTA
    const int gbase = b * NPB + lbase;

    // Register-resident point state
    float x[PPT], y[PPT], z[PPT], dist[PPT];
    unsigned tail[PPT];
#pragma unroll
    for (int p = 0; p < PPT; ++p) {
        float4 v = pts[gbase + p * TPB + tid];
        x[p] = v.y; y[p] = v.z; z[p] = v.w;
        dist[p] = 3.402823466e38f;        // +FLT_MAX: round 1 min == d(.,p0)
        tail[p] = 0x7FFFFFFFu - (unsigned)(lbase + p * TPB + tid);
    }

    // Seed sample = point 0 of the batch
    float4 p0 = pts[(size_t)b * NPB];
    float sx = p0.y, sy = p0.z, sz = p0.w;
    if (c == 0 && tid == 0) {
        float* o = out + (size_t)b * MSAMP * 4;
        o[0] = p0.x; o[1] = p0.y; o[2] = p0.z; o[3] = p0.w;
    }

    __shared__ unsigned s_db[NW], s_tl[NW];
    __shared__ float    s_x[NW], s_y[NW], s_z[NW];
    __shared__ float    s_new[3];

    for (int t = 1; t < MSAMP; ++t) {
        const unsigned tgt = (unsigned)t;

        // ---- local dist update + per-thread argmax (bits compare == float
        // compare for non-negative floats; later equal dist has smaller tail,
        // so strict > keeps the lowest index, matching jnp.argmax) ----
        unsigned bdb = 0u, btl = 0u;
        float bx = 0.f, by = 0.f, bz = 0.f;
#pragma unroll
        for (int p = 0; p < PPT; ++p) {
            float dx = x[p] - sx;
            float dy = y[p] - sy;
            float dz = z[p] - sz;
            // unfused, left-to-right (dx*dx + dy*dy) + dz*dz == reference
            float d  = __fadd_rn(__fadd_rn(__fmul_rn(dx, dx), __fmul_rn(dy, dy)),
                                 __fmul_rn(dz, dz));
            float nd = fminf(dist[p], d);
            dist[p]  = nd;
            unsigned db = __float_as_uint(nd);
            if (db > bdb) { bdb = db; btl = tail[p]; bx = x[p]; by = y[p]; bz = z[p]; }
        }

        // ---- warp argmax via redux (max dist-bits, tie -> max tail = min idx)
        unsigned m  = __reduce_max_sync(0xFFFFFFFFu, bdb);
        unsigned tv = (bdb == m) ? btl : 0u;
        unsigned mt = __reduce_max_sync(0xFFFFFFFFu, tv);
        if (bdb == m && btl == mt) {
            s_db[wid] = bdb; s_tl[wid] = btl;
            s_x[wid] = bx; s_y[wid] = by; s_z[wid] = bz;
        }
        __syncthreads();

        if (wid == 0) {
            // ---- block argmax over NW warp winners (lanes >= NW are dummies)
            unsigned db2 = 0u, tl2 = 0u;
            float x2 = 0.f, y2 = 0.f, z2 = 0.f;
            if (lane < NW) {
                db2 = s_db[lane]; tl2 = s_tl[lane];
                x2 = s_x[lane]; y2 = s_y[lane]; z2 = s_z[lane];
            }
            unsigned m2  = __reduce_max_sync(0xFFFFFFFFu, db2);
            unsigned tv2 = (db2 == m2) ? tl2 : 0u;
            unsigned mt2 = __reduce_max_sync(0xFFFFFFFFu, tv2);
            if (db2 == m2 && tl2 == mt2) {
                // publish this CTA's candidate (both halves self-validating)
                unsigned w = (tgt << 17) | (tl2 & 0x1FFFFu);
                Slot* sp = &g_slot[t & 1][b][c];
                stv(&sp->b, make_uint4(__float_as_uint(z2), w, 0u, 0u));
                stv(&sp->a, make_uint4(db2, w, __float_as_uint(x2),
                                       __float_as_uint(y2)));
            }

            // ---- consume: lane <-> slot, poll until both halves fresh ----
            Slot* sp = &g_slot[t & 1][b][lane];
            uint4 A, Bv;
            do {
                A  = ldv(&sp->a);
                Bv = ldv(&sp->b);
            } while ((A.y >> 17) != tgt || (Bv.y >> 17) != tgt);

            unsigned db3 = A.x;
            unsigned tl3 = 0x7FFE0000u | (A.y & 0x1FFFFu);

            // ---- batch argmax over 32 CTA candidates ----
            unsigned m3  = __reduce_max_sync(0xFFFFFFFFu, db3);
            unsigned tv3 = (db3 == m3) ? tl3 : 0u;
            unsigned mt3 = __reduce_max_sync(0xFFFFFFFFu, tv3);
            if (db3 == m3 && tl3 == mt3) {
                float wx = __uint_as_float(A.z);
                float wy = __uint_as_float(A.w);
                float wz = __uint_as_float(Bv.x);
                s_new[0] = wx; s_new[1] = wy; s_new[2] = wz;
                if (c == 0) {
                    float* o = out + ((size_t)b * MSAMP + t) * 4;
                    o[0] = (float)b; o[1] = wx; o[2] = wy; o[3] = wz;
                }
            }
        }
        __syncthreads();
        sx = s_new[0]; sy = s_new[1]; sz = s_new[2];
    }
}

extern "C" void kernel_launch(void* const* d_in, const int* in_sizes, int n_in,
                              void* d_out, int out_size) {
    (void)in_sizes; (void)n_in; (void)out_size;
    const float4* pts = (const float4*)d_in[0];
    // Geometry fixed by the problem instance: N=262144, B=2, stride=32.
    dim3 grid(CPB, NBATCH);
    fps_kernel<<<grid, TPB>>>(pts, (float*)d_out);
}